// round 1
// baseline (speedup 1.0000x reference)
#include <cuda_runtime.h>

#define Bn  2
#define Cn  3
#define OCn 2
#define Hn  96
#define Wn  96
#define Nn  (Hn*Wn)        // 9216 pixels
#define NPER (Bn*Nn)       // 18432 per-channel count for BN

// Scratch (no allocs allowed): S matrices, BN accumulators, conv output
__device__ float  g_S[Bn][Cn][Cn];     // S[ch][c] * (1/sqrt(3))
__device__ double g_sum[OCn];
__device__ double g_sumsq[OCn];
__device__ float  g_y[Bn*OCn*Nn];

// ---------------------------------------------------------------------------
// K1: S[b][ch][c] = dot(k[b,ch,:], q[b,c,:]) / sqrt(3).  grid (3,3,2) x 256.
// Block (0,0,0) also resets the BN accumulators (graph replays!).
// ---------------------------------------------------------------------------
__global__ void k1_dots(const float* __restrict__ q, const float* __restrict__ k)
{
    const int ch = blockIdx.x, c = blockIdx.y, b = blockIdx.z;
    const float* kr = k + (b*Cn + ch)*Nn;
    const float* qr = q + (b*Cn + c )*Nn;

    float acc = 0.f;
    for (int i = threadIdx.x; i < Nn; i += blockDim.x)
        acc += kr[i] * qr[i];

    __shared__ float sm[8];
    const int lane = threadIdx.x & 31, warp = threadIdx.x >> 5;
    #pragma unroll
    for (int o = 16; o; o >>= 1) acc += __shfl_down_sync(0xffffffffu, acc, o);
    if (lane == 0) sm[warp] = acc;
    __syncthreads();
    if (warp == 0) {
        acc = (lane < 8) ? sm[lane] : 0.f;
        #pragma unroll
        for (int o = 4; o; o >>= 1) acc += __shfl_down_sync(0xffffffffu, acc, o);
        if (lane == 0) {
            g_S[b][ch][c] = acc * 0.57735026918962576451f;  // 1/sqrt(3)
            if (b == 0 && ch == 0 && c == 0) {
                g_sum[0] = 0.0; g_sum[1] = 0.0;
                g_sumsq[0] = 0.0; g_sumsq[1] = 0.0;
            }
        }
    }
}

// ---------------------------------------------------------------------------
// K2: fused agg-reconstruction + 3x3 conv + bias -> g_y, plus BN statistics.
// 72 blocks x 256 threads, one thread per pixel; each block stays in one batch
// (9216 / 256 = 36 blocks per batch).
// ---------------------------------------------------------------------------
__global__ void __launch_bounds__(256)
k2_conv(const float* __restrict__ q, const float* __restrict__ w,
        const float* __restrict__ bias)
{
    __shared__ float sS[Cn][Cn];             // 9
    __shared__ float sW[OCn*Cn*9];           // 54
    __shared__ float red[4][8];

    const int t   = threadIdx.x;
    const int idx = blockIdx.x * 256 + t;    // 0..18431
    const int b   = idx / Nn;
    const int n   = idx - b * Nn;
    const int yy  = n / Wn, xx = n - yy * Wn;

    if (t < Cn*Cn) ((float*)sS)[t] = ((const float*)g_S)[b*Cn*Cn + t];
    if (t < OCn*Cn*9) sW[t] = w[t];
    __syncthreads();

    float acc0 = bias[0];
    float acc1 = bias[1];

    #pragma unroll
    for (int ky = 0; ky < 3; ky++) {
        const int iy = yy + ky - 1;
        #pragma unroll
        for (int kx = 0; kx < 3; kx++) {
            const int ix = xx + kx - 1;
            if (iy >= 0 && iy < Hn && ix >= 0 && ix < Wn) {
                const int m = iy * Wn + ix;
                const float q0 = q[(b*Cn + 0)*Nn + m];
                const float q1 = q[(b*Cn + 1)*Nn + m];
                const float q2 = q[(b*Cn + 2)*Nn + m];
                const float a0 = q0*sS[0][0] + q1*sS[1][0] + q2*sS[2][0];
                const float a1 = q0*sS[0][1] + q1*sS[1][1] + q2*sS[2][1];
                const float a2 = q0*sS[0][2] + q1*sS[1][2] + q2*sS[2][2];
                const int kk = ky*3 + kx;
                acc0 += sW[(0*Cn+0)*9 + kk]*a0 + sW[(0*Cn+1)*9 + kk]*a1 + sW[(0*Cn+2)*9 + kk]*a2;
                acc1 += sW[(1*Cn+0)*9 + kk]*a0 + sW[(1*Cn+1)*9 + kk]*a1 + sW[(1*Cn+2)*9 + kk]*a2;
            }
        }
    }

    g_y[(b*OCn + 0)*Nn + n] = acc0;
    g_y[(b*OCn + 1)*Nn + n] = acc1;

    // BN statistics: block-reduce sum0, sum1, sq0, sq1 then atomic to doubles
    float s0 = acc0, s1 = acc1, s2 = acc0*acc0, s3 = acc1*acc1;
    const int lane = t & 31, warp = t >> 5;
    #pragma unroll
    for (int o = 16; o; o >>= 1) {
        s0 += __shfl_down_sync(0xffffffffu, s0, o);
        s1 += __shfl_down_sync(0xffffffffu, s1, o);
        s2 += __shfl_down_sync(0xffffffffu, s2, o);
        s3 += __shfl_down_sync(0xffffffffu, s3, o);
    }
    if (lane == 0) { red[0][warp]=s0; red[1][warp]=s1; red[2][warp]=s2; red[3][warp]=s3; }
    __syncthreads();
    if (t == 0) {
        float r0=0.f, r1=0.f, r2=0.f, r3=0.f;
        #pragma unroll
        for (int j = 0; j < 8; j++) { r0+=red[0][j]; r1+=red[1][j]; r2+=red[2][j]; r3+=red[3][j]; }
        atomicAdd(&g_sum[0],   (double)r0);
        atomicAdd(&g_sum[1],   (double)r1);
        atomicAdd(&g_sumsq[0], (double)r2);
        atomicAdd(&g_sumsq[1], (double)r3);
    }
}

// ---------------------------------------------------------------------------
// K3: BN (training stats, biased var, eps=1e-5) + affine + LeakyReLU(0.1)
// ---------------------------------------------------------------------------
__global__ void __launch_bounds__(256)
k3_bn(const float* __restrict__ gamma, const float* __restrict__ beta,
      float* __restrict__ out)
{
    const int idx = blockIdx.x * 256 + threadIdx.x;   // 0..36863
    const int c = (idx / Nn) % OCn;
    const float mean = (float)(g_sum[c]   * (1.0 / NPER));
    const float ex2  = (float)(g_sumsq[c] * (1.0 / NPER));
    const float var  = ex2 - mean * mean;
    const float inv  = rsqrtf(var + 1e-5f);
    float v = (g_y[idx] - mean) * inv * gamma[c] + beta[c];
    out[idx] = (v >= 0.f) ? v : 0.1f * v;
}

// ---------------------------------------------------------------------------
extern "C" void kernel_launch(void* const* d_in, const int* in_sizes, int n_in,
                              void* d_out, int out_size)
{
    const float* q      = (const float*)d_in[0];  // X_tnext
    const float* k      = (const float*)d_in[1];  // X_hat_tnext
    const float* conv_w = (const float*)d_in[2];
    const float* conv_b = (const float*)d_in[3];
    const float* gamma  = (const float*)d_in[4];
    const float* beta   = (const float*)d_in[5];
    float* out = (float*)d_out;

    k1_dots<<<dim3(Cn, Cn, Bn), 256>>>(q, k);
    k2_conv<<<NPER/256, 256>>>(q, conv_w, conv_b);
    k3_bn<<<(Bn*OCn*Nn)/256, 256>>>(gamma, beta, out);
}

// round 4
// speedup vs baseline: 1.1779x; 1.1779x over previous
#include <cuda_runtime.h>

#define Bn  2
#define Cn  3
#define OCn 2
#define Hn  96
#define Wn  96
#define Nn  (Hn*Wn)        // 9216 pixels
#define NPER (Bn*Nn)       // 18432 per-channel count for BN

// Scratch (no allocs allowed): S matrices, BN accumulators, conv output
__device__ float  g_S[Bn][Cn][Cn];     // S[ch][c] * (1/sqrt(3))
__device__ double g_sum[OCn];
__device__ double g_sumsq[OCn];
__device__ float  g_y[Bn*OCn*Nn];

// ---------------------------------------------------------------------------
// K1: S[b][ch][c] = dot(k[b,ch,:], q[b,c,:]) / sqrt(3).  grid (3,3,2) x 256.
// float4 + compile-time unroll -> 18 independent LDG.128 in flight per thread.
// Block (0,0,0) also resets the BN accumulators (graph replays!).
// ---------------------------------------------------------------------------
__global__ void __launch_bounds__(256)
k1_dots(const float* __restrict__ q, const float* __restrict__ k)
{
    const int ch = blockIdx.x, c = blockIdx.y, b = blockIdx.z;
    const float4* kr = (const float4*)(k + (b*Cn + ch)*Nn);
    const float4* qr = (const float4*)(q + (b*Cn + c )*Nn);
    const int t = threadIdx.x;

    // 9216/4 = 2304 float4 = 9 * 256
    float p0 = 0.f, p1 = 0.f, p2 = 0.f, p3 = 0.f;
    #pragma unroll
    for (int i = 0; i < 9; i++) {
        const float4 a = kr[t + i*256];
        const float4 bq = qr[t + i*256];
        p0 += a.x*bq.x; p1 += a.y*bq.y; p2 += a.z*bq.z; p3 += a.w*bq.w;
    }
    float acc = (p0 + p1) + (p2 + p3);

    __shared__ float sm[8];
    const int lane = t & 31, warp = t >> 5;
    #pragma unroll
    for (int o = 16; o; o >>= 1) acc += __shfl_down_sync(0xffffffffu, acc, o);
    if (lane == 0) sm[warp] = acc;
    __syncthreads();
    if (warp == 0) {
        acc = (lane < 8) ? sm[lane] : 0.f;
        #pragma unroll
        for (int o = 4; o; o >>= 1) acc += __shfl_down_sync(0xffffffffu, acc, o);
        if (lane == 0) {
            g_S[b][ch][c] = acc * 0.57735026918962576451f;  // 1/sqrt(3)
            if (b == 0 && ch == 0 && c == 0) {
                g_sum[0] = 0.0; g_sum[1] = 0.0;
                g_sumsq[0] = 0.0; g_sumsq[1] = 0.0;
            }
        }
    }
}

// ---------------------------------------------------------------------------
// K2: fused agg-reconstruction + 3x3 conv + bias -> g_y, plus BN statistics.
// 72 blocks x 256 threads, one thread per pixel.
// ---------------------------------------------------------------------------
__global__ void __launch_bounds__(256)
k2_conv(const float* __restrict__ q, const float* __restrict__ w,
        const float* __restrict__ bias)
{
    __shared__ float sS[Cn][Cn];             // 9
    __shared__ float sW[OCn*Cn*9];           // 54
    __shared__ float red[4][8];

    const int t   = threadIdx.x;
    const int idx = blockIdx.x * 256 + t;    // 0..18431
    const int b   = idx / Nn;
    const int n   = idx - b * Nn;
    const int yy  = n / Wn, xx = n - yy * Wn;

    if (t < Cn*Cn) ((float*)sS)[t] = ((const float*)g_S)[b*Cn*Cn + t];
    if (t < OCn*Cn*9) sW[t] = w[t];
    __syncthreads();

    float acc0 = bias[0];
    float acc1 = bias[1];

    #pragma unroll
    for (int ky = 0; ky < 3; ky++) {
        const int iy = yy + ky - 1;
        #pragma unroll
        for (int kx = 0; kx < 3; kx++) {
            const int ix = xx + kx - 1;
            if (iy >= 0 && iy < Hn && ix >= 0 && ix < Wn) {
                const int m = iy * Wn + ix;
                const float q0 = q[(b*Cn + 0)*Nn + m];
                const float q1 = q[(b*Cn + 1)*Nn + m];
                const float q2 = q[(b*Cn + 2)*Nn + m];
                const float a0 = q0*sS[0][0] + q1*sS[1][0] + q2*sS[2][0];
                const float a1 = q0*sS[0][1] + q1*sS[1][1] + q2*sS[2][1];
                const float a2 = q0*sS[0][2] + q1*sS[1][2] + q2*sS[2][2];
                const int kk = ky*3 + kx;
                acc0 += sW[(0*Cn+0)*9 + kk]*a0 + sW[(0*Cn+1)*9 + kk]*a1 + sW[(0*Cn+2)*9 + kk]*a2;
                acc1 += sW[(1*Cn+0)*9 + kk]*a0 + sW[(1*Cn+1)*9 + kk]*a1 + sW[(1*Cn+2)*9 + kk]*a2;
            }
        }
    }

    g_y[(b*OCn + 0)*Nn + n] = acc0;
    g_y[(b*OCn + 1)*Nn + n] = acc1;

    // BN statistics: block-reduce sum0, sum1, sq0, sq1 then atomic to doubles
    float s0 = acc0, s1 = acc1, s2 = acc0*acc0, s3 = acc1*acc1;
    const int lane = t & 31, warp = t >> 5;
    #pragma unroll
    for (int o = 16; o; o >>= 1) {
        s0 += __shfl_down_sync(0xffffffffu, s0, o);
        s1 += __shfl_down_sync(0xffffffffu, s1, o);
        s2 += __shfl_down_sync(0xffffffffu, s2, o);
        s3 += __shfl_down_sync(0xffffffffu, s3, o);
    }
    if (lane == 0) { red[0][warp]=s0; red[1][warp]=s1; red[2][warp]=s2; red[3][warp]=s3; }
    __syncthreads();
    if (t == 0) {
        float r0=0.f, r1=0.f, r2=0.f, r3=0.f;
        #pragma unroll
        for (int j = 0; j < 8; j++) { r0+=red[0][j]; r1+=red[1][j]; r2+=red[2][j]; r3+=red[3][j]; }
        atomicAdd(&g_sum[0],   (double)r0);
        atomicAdd(&g_sum[1],   (double)r1);
        atomicAdd(&g_sumsq[0], (double)r2);
        atomicAdd(&g_sumsq[1], (double)r3);
    }
}

// ---------------------------------------------------------------------------
// K3: BN (training stats, biased var, eps=1e-5) + affine + LeakyReLU(0.1)
// ---------------------------------------------------------------------------
__global__ void __launch_bounds__(256)
k3_bn(const float* __restrict__ gamma, const float* __restrict__ beta,
      float* __restrict__ out)
{
    const int idx = blockIdx.x * 256 + threadIdx.x;   // 0..36863
    const int c = (idx / Nn) % OCn;
    const float mean = (float)(g_sum[c]   * (1.0 / NPER));
    const float ex2  = (float)(g_sumsq[c] * (1.0 / NPER));
    const float var  = ex2 - mean * mean;
    const float inv  = rsqrtf(var + 1e-5f);
    float v = (g_y[idx] - mean) * inv * gamma[c] + beta[c];
    out[idx] = (v >= 0.f) ? v : 0.1f * v;
}

// ---------------------------------------------------------------------------
extern "C" void kernel_launch(void* const* d_in, const int* in_sizes, int n_in,
                              void* d_out, int out_size)
{
    const float* q      = (const float*)d_in[0];  // X_tnext
    const float* k      = (const float*)d_in[1];  // X_hat_tnext
    const float* conv_w = (const float*)d_in[2];
    const float* conv_b = (const float*)d_in[3];
    const float* gamma  = (const float*)d_in[4];
    const float* beta   = (const float*)d_in[5];
    float* out = (float*)d_out;

    k1_dots<<<dim3(Cn, Cn, Bn), 256>>>(q, k);
    k2_conv<<<NPER/256, 256>>>(q, conv_w, conv_b);
    k3_bn<<<(Bn*OCn*Nn)/256, 256>>>(gamma, beta, out);
}